// round 5
// baseline (speedup 1.0000x reference)
#include <cuda_runtime.h>
#include <stdint.h>
#include <math.h>

#define DN 256
#define NN 128
#define SD 132            // scratch row stride (floats)
#define NTHREADS 1024
#define SMEM_BYTES (129 * SD * 4)

// Master matrix: G eliminated through current front t (device-global scratch).
__device__ float g_A[DN * DN];
// Shadow diagonal chain: (G[q,q]-1) followed by exactly the same update chain
// the master diagonal receives (reference has the -1 present from step 0).
__device__ float g_dv1[DN];
// Precomputed gumbel noise per (step k, position i) — data independent.
__device__ float g_gum[NN * DN];

// ---------------------------------------------------------------------------
// Threefry-2x32, 20 rounds (JAX-compatible, verified vs Random123 schedule)
// ---------------------------------------------------------------------------
__device__ __forceinline__ void threefry(uint32_t k0, uint32_t k1,
                                         uint32_t x0, uint32_t x1,
                                         uint32_t &o0, uint32_t &o1)
{
    uint32_t ks2 = k0 ^ k1 ^ 0x1BD11BDAu;
#define TFR(r) { x0 += x1; x1 = (x1 << r) | (x1 >> (32 - r)); x1 ^= x0; }
    x0 += k0; x1 += k1;
    TFR(13) TFR(15) TFR(26) TFR(6)
    x0 += k1;  x1 += ks2 + 1u;
    TFR(17) TFR(29) TFR(16) TFR(24)
    x0 += ks2; x1 += k0 + 2u;
    TFR(13) TFR(15) TFR(26) TFR(6)
    x0 += k0;  x1 += k1 + 3u;
    TFR(17) TFR(29) TFR(16) TFR(24)
    x0 += k1;  x1 += ks2 + 4u;
    TFR(13) TFR(15) TFR(26) TFR(6)
    x0 += ks2; x1 += k0 + 5u;
#undef TFR
    o0 = x0; o1 = x1;
}

// ---------------------------------------------------------------------------
// G = I - P P^T  (exact fp32, serial ascending-k fma accumulation)
// ---------------------------------------------------------------------------
__global__ void g_init_kernel(const float* __restrict__ P)
{
    __shared__ float Ta[16][129];
    __shared__ float Tb[16][129];
    const int bi = blockIdx.y * 16;
    const int bj = blockIdx.x * 16;
    for (int e = threadIdx.x; e < 16 * 128; e += 256) {
        int r = e >> 7, c = e & 127;
        Ta[r][c] = P[(bi + r) * 128 + c];
        Tb[r][c] = P[(bj + r) * 128 + c];
    }
    __syncthreads();
    const int ty = threadIdx.x >> 4, tx = threadIdx.x & 15;
    float acc = 0.0f;
#pragma unroll 8
    for (int m = 0; m < 128; m++)
        acc = __fmaf_rn(Ta[ty][m], Tb[tx][m], acc);
    const int gi = bi + ty, gj = bj + tx;
    g_A[gi * DN + gj] = __fsub_rn((gi == gj) ? 1.0f : 0.0f, acc);
}

// ---------------------------------------------------------------------------
// Precompute gumbel noise — JAX *partitionable* threefry bits path:
//   counter64 = i  ->  threefry(key, hi32=0, lo32=i) -> bits = o0 ^ o1
// key = fold_in(key(42), k) = threefry((0,42), (0,k))  [fold_in is flag-free]
// ---------------------------------------------------------------------------
__global__ void gumbel_init_kernel()
{
    const int k = blockIdx.x;      // step
    const int i = threadIdx.x;     // position 0..255
    uint32_t kk0, kk1;
    threefry(0u, 42u, 0u, (uint32_t)k, kk0, kk1);     // fold_in(key(42), k)
    uint32_t o0, o1;
    threefry(kk0, kk1, 0u, (uint32_t)i, o0, o1);      // counter64 = i
    const uint32_t bits = o0 ^ o1;                     // 64->32 fold
    const float f = __uint_as_float((bits >> 9) | 0x3f800000u) - 1.0f;
    const float TINYF = 1.17549435e-38f;
    const float uu = fmaxf(TINYF, __fadd_rn(f, TINYF));
    const float nl = (float)(-log((double)uu));
    const float g  = -(float)(log((double)nl));
    g_gum[k * DN + i] = g;
}

// ---------------------------------------------------------------------------
// Persistent single-CTA sampler: 128 sequential steps (incremental front).
// ---------------------------------------------------------------------------
__global__ __launch_bounds__(NTHREADS, 1)
void sampler_kernel(float* __restrict__ out, int out_size)
{
    extern __shared__ float S[];          // scratch block, SD-stride rows
    __shared__ float piv[DN];
    __shared__ float probs[DN];
    __shared__ float occ[DN];
    __shared__ float um[DN];
    __shared__ float tr[512];             // associative-scan down-sweep levels
    __shared__ float ts[512];             // associative-scan up-sweep levels
    __shared__ float wr[32];
    __shared__ int   wi[32];
    __shared__ int   sh_t, sh_pos;
    __shared__ float sh_ps;

    const int tid = threadIdx.x;
    const int wid = tid >> 5, lid = tid & 31;
    const float NEGINF = __int_as_float(0xff800000);
    const int offs[9] = {0, 256, 384, 448, 480, 496, 504, 508, 510};

    for (int i = tid; i < DN; i += NTHREADS) {
        occ[i] = 0.0f;
        g_dv1[i] = __fsub_rn(g_A[i * DN + i], 1.0f);
    }
    if (tid == 0) { sh_t = 0; sh_ps = 1.0f; }
    __syncthreads();

    for (int k = 0; k < NN; k++) {
        const int t = sh_t;
        const int xmax = DN - NN + k + 1;   // 129 + k
        const int s = xmax - t;             // <= 129

        // ---- copy active master block [t:xmax)^2 into shared scratch ----
        for (int r = wid; r < s; r += 32) {
            const float* src = g_A + (t + r) * DN + t;
            float* dst = S + r * SD;
            for (int c = lid; c < s; c += 32) dst[c] = src[c];
        }
        __syncthreads();

        // ---- speculative elimination: record pivots u[t..xmax) ----
        for (int j = 0; j < s; j++) {
            const float pv = S[j * SD + j];
            if (tid == 0) piv[t + j] = pv;
            const float pvs = (fabsf(pv) > 1e-30f) ? pv : 1e-30f;
            const int cc = j + 1 + lid;
            const float* uro = S + j * SD;
            const float u0 = (cc      < s) ? uro[cc     ] : 0.0f;
            const float u1 = (cc + 32 < s) ? uro[cc + 32] : 0.0f;
            const float u2 = (cc + 64 < s) ? uro[cc + 64] : 0.0f;
            const float u3 = (cc + 96 < s) ? uro[cc + 96] : 0.0f;
            for (int i = j + 1 + wid; i < s; i += 32) {
                const float li = __fdiv_rn(S[i * SD + j], pvs);
                float* row = S + i * SD;
                if (cc      < s) row[cc     ] = __fsub_rn(row[cc     ], __fmul_rn(li, u0));
                if (cc + 32 < s) row[cc + 32] = __fsub_rn(row[cc + 32], __fmul_rn(li, u1));
                if (cc + 64 < s) row[cc + 64] = __fsub_rn(row[cc + 64], __fmul_rn(li, u2));
                if (cc + 96 < s) row[cc + 96] = __fsub_rn(row[cc + 96], __fmul_rn(li, u3));
            }
            __syncthreads();
        }

        // ---- u_m (masked pivots) ----
        for (int i = tid; i < DN; i += NTHREADS)
            um[i] = (i >= t && i < xmax) ? piv[i] : 1.0f;
        __syncthreads();

        // ---- cumprod via associative-scan tree ----
        for (int i = tid; i < DN; i += NTHREADS) tr[i] = um[i];
        __syncthreads();
        for (int L = 1; L <= 8; L++) {
            const int n = DN >> L;
            for (int i = tid; i < n; i += NTHREADS)
                tr[offs[L] + i] = __fmul_rn(tr[offs[L-1] + 2*i], tr[offs[L-1] + 2*i + 1]);
            __syncthreads();
        }
        if (tid == 0) ts[offs[8]] = tr[offs[8]];
        __syncthreads();
        for (int L = 7; L >= 0; L--) {
            const int n = DN >> L;
            for (int i = tid; i < n; i += NTHREADS) {
                float v;
                if (i == 0)       v = tr[offs[L]];
                else if (i & 1)   v = ts[offs[L+1] + ((i - 1) >> 1)];
                else              v = __fmul_rn(ts[offs[L+1] + (i >> 1) - 1], tr[offs[L] + i]);
                ts[offs[L] + i] = v;
            }
            __syncthreads();
        }

        // ---- probs on support ----
        for (int j = tid; j < DN; j += NTHREADS) {
            if (j >= t && j < xmax) {
                const float c = (j == 0) ? 1.0f : ts[j - 1];
                const float p = __fmul_rn(__fsub_rn(1.0f, um[j]), c);
                probs[j] = (fabsf(p) > 1e-15f) ? p : 0.0f;
            } else {
                probs[j] = 0.0f;
            }
        }
        __syncthreads();

        // ---- gumbel-categorical argmax (gumbel precomputed) ----
        float v = NEGINF;
        int bi = 1 << 30;
        if (tid < DN) {
            const float p = probs[tid];
            const float logit = (p > 0.0f) ? (float)(log((double)p)) : NEGINF;
            v = __fadd_rn(g_gum[k * DN + tid], logit);
            bi = tid;
        }
        for (int off = 16; off; off >>= 1) {
            const float ov = __shfl_down_sync(0xffffffffu, v, off);
            const int   oi = __shfl_down_sync(0xffffffffu, bi, off);
            if (ov > v || (ov == v && oi < bi)) { v = ov; bi = oi; }
        }
        if (lid == 0) { wr[wid] = v; wi[wid] = bi; }
        __syncthreads();
        if (tid == 0) {
            float bv = wr[0]; int bx = wi[0];
            for (int w = 1; w < 8; w++)
                if (wr[w] > bv || (wr[w] == bv && wi[w] < bx)) { bv = wr[w]; bx = wi[w]; }
            sh_pos = bx;
            occ[bx] = 1.0f;
            sh_ps = __fmul_rn(sh_ps, probs[bx]);
        }
        __syncthreads();

        // ---- commit rows t..pos into master (advance front to pos+1) ----
        const int pos = sh_pos;
        if (k < NN - 1) {
            for (int j = t; j <= pos; j++) {
                if (tid == 0 && j == pos)
                    g_A[pos * DN + pos] = g_dv1[pos];   // ref-exact (-1 from step 0) chain
                __syncthreads();
                const float pv = g_A[j * DN + j];
                const float pvs = (fabsf(pv) > 1e-30f) ? pv : 1e-30f;
                const int cc = j + 1 + lid;
                const float* uro = g_A + j * DN;
                float uu[8];
#pragma unroll
                for (int m = 0; m < 8; m++) {
                    const int c = cc + 32 * m;
                    uu[m] = (c < DN) ? uro[c] : 0.0f;
                }
                for (int i = j + 1 + wid; i < DN; i += 32) {
                    const float li = __fdiv_rn(g_A[i * DN + j], pvs);
                    float* row = g_A + i * DN;
#pragma unroll
                    for (int m = 0; m < 8; m++) {
                        const int c = cc + 32 * m;
                        if (c < DN) {
                            const float x = __fmul_rn(li, uu[m]);
                            row[c] = __fsub_rn(row[c], x);
                            if (c == i) g_dv1[i] = __fsub_rn(g_dv1[i], x);
                        }
                    }
                }
                __syncthreads();
            }
            if (tid == 0) sh_t = pos + 1;
        }
        __syncthreads();
    }

    // ---- outputs: occ_vec (256) then prob_sample (1) ----
    for (int i = tid; i < DN && i < out_size; i += NTHREADS) out[i] = occ[i];
    if (tid == 0 && out_size > DN) out[DN] = sh_ps;
    for (int i = DN + 1 + tid; i < out_size; i += NTHREADS) out[i] = 0.0f;
}

// ---------------------------------------------------------------------------
extern "C" void kernel_launch(void* const* d_in, const int* in_sizes, int n_in,
                              void* d_out, int out_size)
{
    const float* P = (const float*)d_in[0];
    float* out = (float*)d_out;

    cudaFuncSetAttribute(sampler_kernel,
                         cudaFuncAttributeMaxDynamicSharedMemorySize,
                         SMEM_BYTES);

    g_init_kernel<<<dim3(16, 16), 256>>>(P);
    gumbel_init_kernel<<<NN, DN>>>();
    sampler_kernel<<<1, NTHREADS, SMEM_BYTES>>>(out, out_size);
}